// round 12
// baseline (speedup 1.0000x reference)
#include <cuda_runtime.h>
#include <cuda_bf16.h>
#include <cstdint>
#include <math.h>

// Problem constants
#define BROWS 8192
#define DIM   512
#define INV_T 14.285714285714286f   // 1/0.07

// Tiling: CTA 128x128 = 4 warps x (64x64), mma m16n8k16 bf16
#define TM 128
#define TN 128
#define KC 64                        // bf16 elements per chunk (128B rows)
#define NCHUNK (DIM / KC)            // 8
#define NB (BROWS / TM)              // 64 blocks per dim
#define NTILES (NB * (NB + 1) / 2)   // 2080 lower-tri tiles
#define NTHREADS 128

#define TILE_BYTES  (128 * 128)      // one 128-row x 128B tile (16 KB)
#define STAGE_BYTES (2 * TILE_BYTES) // A + B (32 KB)
#define STAGES 2
#define SMEM_BYTES  (STAGES * STAGE_BYTES)   // 64 KB -> occ 3

#define SWZ(o) ((o) ^ (((o) >> 3) & 0x70))

// Scratch (static device globals — no allocation)
__device__ __nv_bfloat16 g_f[BROWS * DIM];   // bf16 normalized features (8 MB)
__device__ float g_partial[NB][BROWS];       // per-block exp row sums
__device__ float g_rowval[BROWS];

// ---------------------------------------------------------------------------
__device__ __forceinline__ uint32_t smem_u32(const void* p) {
    uint32_t a;
    asm("{ .reg .u64 t; cvta.to.shared.u64 t, %1; cvt.u32.u64 %0, t; }"
        : "=r"(a) : "l"(p));
    return a;
}
__device__ __forceinline__ void cp16(uint32_t dst, const void* src) {
    asm volatile("cp.async.cg.shared.global [%0], [%1], 16;"
                 :: "r"(dst), "l"(src) : "memory");
}
__device__ __forceinline__ void ldsm_x4(uint32_t* r, uint32_t addr) {
    asm volatile("ldmatrix.sync.aligned.m8n8.x4.shared.b16 {%0,%1,%2,%3}, [%4];"
                 : "=r"(r[0]), "=r"(r[1]), "=r"(r[2]), "=r"(r[3]) : "r"(addr));
}
__device__ __forceinline__ void mma_bf16(float* c, const uint32_t* a,
                                         uint32_t b0, uint32_t b1) {
    asm volatile(
        "mma.sync.aligned.m16n8k16.row.col.f32.bf16.bf16.f32 "
        "{%0,%1,%2,%3}, {%4,%5,%6,%7}, {%8,%9}, {%0,%1,%2,%3};"
        : "+f"(c[0]), "+f"(c[1]), "+f"(c[2]), "+f"(c[3])
        : "r"(a[0]), "r"(a[1]), "r"(a[2]), "r"(a[3]), "r"(b0), "r"(b1));
}

// ---------------------------------------------------------------------------
// Kernel A: row L2-normalize + round to bf16
// ---------------------------------------------------------------------------
__global__ void normalize_kernel(const float* __restrict__ x) {
    int row  = blockIdx.x * 8 + threadIdx.y;
    int lane = threadIdx.x;
    const float* xr = x + (size_t)row * DIM;
    float v[16];
    float s = 0.f;
#pragma unroll
    for (int i = 0; i < 16; i++) { v[i] = xr[lane + i * 32]; s += v[i] * v[i]; }
#pragma unroll
    for (int o = 16; o; o >>= 1) s += __shfl_xor_sync(0xffffffffu, s, o);
    float inv = 1.0f / fmaxf(sqrtf(s), 1e-12f);
    __nv_bfloat16* fr = g_f + (size_t)row * DIM;
#pragma unroll
    for (int i = 0; i < 16; i++)
        fr[lane + i * 32] = __float2bfloat16_rn(v[i] * inv);
}

// ---------------------------------------------------------------------------
// Kernel B: bf16 mma.sync GEMM, lower-tri tiles, cp.async 2-stage / occ 3.
// 4 warps of 64x64. Schedule: issue(c+1) -> wait_group(1) -> sync -> compute
// -> sync. wait_group(1) leaves only the just-issued group pending, so the
// chunk about to be computed is fully resident.
// ---------------------------------------------------------------------------
extern __shared__ char dynsm[];

__global__ __launch_bounds__(NTHREADS, 3) void gemm_lse_mma() {
    __shared__ float red_r[TM][2];
    __shared__ float red_c[TN][2];

    const int tid  = threadIdx.x;
    const int wid  = tid >> 5;
    const int lane = tid & 31;
    const int wr   = wid & 1;        // warp row (M chunks of 64)
    const int wc   = wid >> 1;       // warp col (N chunks of 64)
    const int g    = lane >> 2;
    const int t    = lane & 3;

    // decode lower-tri pair (bi >= bj)
    int idx = blockIdx.x;
    int bi = (int)((sqrtf(8.0f * (float)idx + 1.0f) - 1.0f) * 0.5f);
    while ((bi + 1) * (bi + 2) / 2 <= idx) bi++;
    while (bi * (bi + 1) / 2 > idx) bi--;
    int bj = idx - bi * (bi + 1) / 2;
    const int r0 = bi * TM;
    const int j0 = bj * TN;
    const bool offdiag = (bi != bj);

    const __nv_bfloat16* srcA = g_f + (size_t)r0 * DIM;
    const __nv_bfloat16* srcB = g_f + (size_t)j0 * DIM;

    const uint32_t smem_base = smem_u32(dynsm);

    const int srow = tid >> 3;       // 0..15; +16 per iter (8 iters = 128 rows)
    const int sseg = tid & 7;

    const int a_row  = wr * 64 + (lane & 15);
    const int a_koff = (lane >> 4) * 16;
    const int b_row  = wc * 64 + (lane & 7) + ((lane >> 4) << 3);
    const int b_koff = ((lane >> 3) & 1) * 16;

    float acc[4][8][4];
#pragma unroll
    for (int mt = 0; mt < 4; mt++)
#pragma unroll
        for (int nt = 0; nt < 8; nt++)
#pragma unroll
            for (int rr = 0; rr < 4; rr++) acc[mt][nt][rr] = 0.f;

    auto issue_chunk = [&](int c, int s) {
        const uint32_t sa = smem_base + s * STAGE_BYTES;
        const int ko = c * KC;
#pragma unroll
        for (int it = 0; it < 8; it++) {
            int row = srow + it * 16;
            uint32_t off = SWZ(row * 128 + sseg * 16);
            cp16(sa + off, srcA + (size_t)row * DIM + ko + sseg * 8);
            cp16(sa + TILE_BYTES + off, srcB + (size_t)row * DIM + ko + sseg * 8);
        }
        asm volatile("cp.async.commit_group;" ::: "memory");
    };

    // prologue: stage 0
    issue_chunk(0, 0);

    for (int c = 0; c < NCHUNK; c++) {
        if (c + 1 < NCHUNK) {
            issue_chunk(c + 1, (c + 1) & 1);
            asm volatile("cp.async.wait_group 1;" ::: "memory");
        } else {
            asm volatile("cp.async.wait_group 0;" ::: "memory");
        }
        __syncthreads();

        const uint32_t sa = smem_base + (c & 1) * STAGE_BYTES;
        const uint32_t sb = sa + TILE_BYTES;

#pragma unroll
        for (int kstep = 0; kstep < 4; kstep++) {
            uint32_t afr[4][4];
#pragma unroll
            for (int mt = 0; mt < 4; mt++) {
                int off = SWZ((a_row + mt * 16) * 128 + kstep * 32 + a_koff);
                ldsm_x4(afr[mt], sa + off);
            }
            uint32_t bfr[8][2];
#pragma unroll
            for (int p = 0; p < 4; p++) {
                uint32_t r[4];
                int off = SWZ((b_row + p * 16) * 128 + kstep * 32 + b_koff);
                ldsm_x4(r, sb + off);
                bfr[2 * p][0] = r[0]; bfr[2 * p][1] = r[1];
                bfr[2 * p + 1][0] = r[2]; bfr[2 * p + 1][1] = r[3];
            }
#pragma unroll
            for (int mt = 0; mt < 4; mt++)
#pragma unroll
                for (int nt = 0; nt < 8; nt++)
                    mma_bf16(acc[mt][nt], afr[mt], bfr[nt][0], bfr[nt][1]);
        }
        __syncthreads();   // all reads of this stage done before reuse
    }

    // ---- epilogue: exp in place; row sums + col sums (off-diag) ----
#pragma unroll
    for (int mt = 0; mt < 4; mt++)
#pragma unroll
        for (int nt = 0; nt < 8; nt++)
#pragma unroll
            for (int rr = 0; rr < 4; rr++)
                acc[mt][nt][rr] = __expf((acc[mt][nt][rr] - 1.0f) * INV_T);

    // row sums: row = wr*64 + mt*16 + hi*8 + g, reduce over t (lanes ^1,^2)
#pragma unroll
    for (int mt = 0; mt < 4; mt++)
#pragma unroll
        for (int hi = 0; hi < 2; hi++) {
            float s = 0.f;
#pragma unroll
            for (int nt = 0; nt < 8; nt++)
                s += acc[mt][nt][hi * 2 + 0] + acc[mt][nt][hi * 2 + 1];
            s += __shfl_xor_sync(0xffffffffu, s, 1);
            s += __shfl_xor_sync(0xffffffffu, s, 2);
            if (t == 0) red_r[wr * 64 + mt * 16 + hi * 8 + g][wc] = s;
        }

    // col sums: col = wc*64 + nt*8 + t*2 + {0,1}; sum over mt, reduce over g
    if (offdiag) {
#pragma unroll
        for (int nt = 0; nt < 8; nt++) {
            float cs0 = 0.f, cs1 = 0.f;
#pragma unroll
            for (int mt = 0; mt < 4; mt++) {
                cs0 += acc[mt][nt][0] + acc[mt][nt][2];
                cs1 += acc[mt][nt][1] + acc[mt][nt][3];
            }
#pragma unroll
            for (int o = 4; o <= 16; o <<= 1) {
                cs0 += __shfl_xor_sync(0xffffffffu, cs0, o);
                cs1 += __shfl_xor_sync(0xffffffffu, cs1, o);
            }
            if (g == 0) {
                red_c[wc * 64 + nt * 8 + t * 2 + 0][wr] = cs0;
                red_c[wc * 64 + nt * 8 + t * 2 + 1][wr] = cs1;
            }
        }
    }
    __syncthreads();

    // 128 threads, one row each
    g_partial[bj][r0 + tid] = red_r[tid][0] + red_r[tid][1];
    if (offdiag)
        g_partial[bi][j0 + tid] = red_c[tid][0] + red_c[tid][1];
}

// ---------------------------------------------------------------------------
// Kernel C: labels (col 0/1), picked dot (bf16 inputs, fp32 accum), lse
// ---------------------------------------------------------------------------
__global__ void pick_kernel(const int* __restrict__ ids,
                            const int* __restrict__ anchor) {
    int row  = blockIdx.x * 8 + threadIdx.y;
    int lane = threadIdx.x;

    int aid       = ids[anchor[0]];
    int same_last = (ids[BROWS - 1] == aid);
    int label;
    if (row == BROWS - 1)
        label = (same_last && (ids[BROWS - 2] == aid)) ? 1 : 0;
    else
        label = ((ids[row] == aid) && same_last) ? 1 : 0;

    const __nv_bfloat16* fi = g_f + (size_t)row * DIM;
    const __nv_bfloat16* fc = g_f + (size_t)label * DIM;
    float d = 0.f;
#pragma unroll
    for (int i = 0; i < 16; i++)
        d = fmaf(__bfloat162float(fi[lane + i * 32]),
                 __bfloat162float(fc[lane + i * 32]), d);

    // parallel partial-slot sum: lanes each grab 2 of the 64 slots
    float rs = g_partial[lane][row] + g_partial[lane + 32][row];

#pragma unroll
    for (int o = 16; o; o >>= 1) {
        d  += __shfl_xor_sync(0xffffffffu, d, o);
        rs += __shfl_xor_sync(0xffffffffu, rs, o);
    }

    if (lane == 0) {
        float lse = INV_T + logf(rs);
        g_rowval[row] = lse - d * INV_T;
    }
}

// ---------------------------------------------------------------------------
// Kernel D: deterministic final reduction (1024 threads)
// ---------------------------------------------------------------------------
__global__ void finalize_kernel(float* __restrict__ out) {
    __shared__ float sm[32];
    int tdx = threadIdx.x;
    float s = 0.f;
#pragma unroll
    for (int i = 0; i < 8; i++) s += g_rowval[tdx + i * 1024];
#pragma unroll
    for (int o = 16; o; o >>= 1) s += __shfl_xor_sync(0xffffffffu, s, o);
    if ((tdx & 31) == 0) sm[tdx >> 5] = s;
    __syncthreads();
    if (tdx < 32) {
        float v = sm[tdx];
#pragma unroll
        for (int o = 16; o; o >>= 1) v += __shfl_xor_sync(0xffffffffu, v, o);
        if (tdx == 0) out[0] = v / (float)BROWS;
    }
}

// ---------------------------------------------------------------------------
extern "C" void kernel_launch(void* const* d_in, const int* in_sizes, int n_in,
                              void* d_out, int out_size) {
    const float* feat   = (const float*)d_in[0];
    const int*   ids    = (const int*)d_in[1];
    const int*   anchor = (const int*)d_in[2];
    float*       out    = (float*)d_out;

    cudaFuncSetAttribute(gemm_lse_mma,
                         cudaFuncAttributeMaxDynamicSharedMemorySize, SMEM_BYTES);

    dim3 b32x8(32, 8);
    normalize_kernel<<<BROWS / 8, b32x8>>>(feat);

    gemm_lse_mma<<<NTILES, NTHREADS, SMEM_BYTES>>>();

    pick_kernel<<<BROWS / 8, b32x8>>>(ids, anchor);
    finalize_kernel<<<1, 1024>>>(out);
}

// round 13
// speedup vs baseline: 1.1510x; 1.1510x over previous
#include <cuda_runtime.h>
#include <cuda_bf16.h>
#include <cstdint>
#include <math.h>

// Problem constants
#define BROWS 8192
#define DIM   512
#define INV_T 14.285714285714286f   // 1/0.07

// Tiling: CTA 128x128 = 4 warps x (64x64), mma m16n8k16 bf16
#define TM 128
#define TN 128
#define KC 64                        // bf16 elements per chunk (128B rows)
#define NCHUNK (DIM / KC)            // 8
#define NB (BROWS / TM)              // 64 blocks per dim
#define NTILES (NB * (NB + 1) / 2)   // 2080 lower-tri tiles
#define NTHREADS 128

#define TILE_BYTES  (128 * 128)      // one 128-row x 128B tile (16 KB)
#define STAGE_BYTES (2 * TILE_BYTES) // A + B (32 KB)
#define STAGES 3
#define SMEM_BYTES  (STAGES * STAGE_BYTES)   // 96 KB -> occ 2

#define SWZ(o) ((o) ^ (((o) >> 3) & 0x70))

// Scratch (static device globals — no allocation)
__device__ __nv_bfloat16 g_f[BROWS * DIM];   // bf16 normalized features (8 MB)
__device__ float g_partial[NB][BROWS];       // per-block exp row sums
__device__ float g_rowval[BROWS];

// ---------------------------------------------------------------------------
__device__ __forceinline__ uint32_t smem_u32(const void* p) {
    uint32_t a;
    asm("{ .reg .u64 t; cvta.to.shared.u64 t, %1; cvt.u32.u64 %0, t; }"
        : "=r"(a) : "l"(p));
    return a;
}
__device__ __forceinline__ void cp16(uint32_t dst, const void* src) {
    asm volatile("cp.async.cg.shared.global [%0], [%1], 16;"
                 :: "r"(dst), "l"(src) : "memory");
}
__device__ __forceinline__ void ldsm_x4(uint32_t* r, uint32_t addr) {
    asm volatile("ldmatrix.sync.aligned.m8n8.x4.shared.b16 {%0,%1,%2,%3}, [%4];"
                 : "=r"(r[0]), "=r"(r[1]), "=r"(r[2]), "=r"(r[3]) : "r"(addr));
}
__device__ __forceinline__ void mma_bf16(float* c, const uint32_t* a,
                                         uint32_t b0, uint32_t b1) {
    asm volatile(
        "mma.sync.aligned.m16n8k16.row.col.f32.bf16.bf16.f32 "
        "{%0,%1,%2,%3}, {%4,%5,%6,%7}, {%8,%9}, {%0,%1,%2,%3};"
        : "+f"(c[0]), "+f"(c[1]), "+f"(c[2]), "+f"(c[3])
        : "r"(a[0]), "r"(a[1]), "r"(a[2]), "r"(a[3]), "r"(b0), "r"(b1));
}
__device__ __forceinline__ float dot8_bf16(uint4 a, uint4 b) {
    const __nv_bfloat162* pa = (const __nv_bfloat162*)&a;
    const __nv_bfloat162* pb = (const __nv_bfloat162*)&b;
    float s = 0.f;
#pragma unroll
    for (int i = 0; i < 4; i++) {
        float2 fa = __bfloat1622float2(pa[i]);
        float2 fb = __bfloat1622float2(pb[i]);
        s = fmaf(fa.x, fb.x, s);
        s = fmaf(fa.y, fb.y, s);
    }
    return s;
}

// ---------------------------------------------------------------------------
// Kernel A: row L2-normalize + round to bf16 (float4 I/O)
// ---------------------------------------------------------------------------
__global__ void normalize_kernel(const float* __restrict__ x) {
    int row  = blockIdx.x * 8 + threadIdx.y;
    int lane = threadIdx.x;
    const float4* xr = (const float4*)(x + (size_t)row * DIM) + lane * 4;
    float4 v[4];
    float s = 0.f;
#pragma unroll
    for (int i = 0; i < 4; i++) {
        v[i] = xr[i];
        s += v[i].x * v[i].x + v[i].y * v[i].y + v[i].z * v[i].z + v[i].w * v[i].w;
    }
#pragma unroll
    for (int o = 16; o; o >>= 1) s += __shfl_xor_sync(0xffffffffu, s, o);
    float inv = 1.0f / fmaxf(sqrtf(s), 1e-12f);
    __nv_bfloat162* fr = (__nv_bfloat162*)(g_f + (size_t)row * DIM) + lane * 8;
#pragma unroll
    for (int i = 0; i < 4; i++) {
        fr[i * 2 + 0] = __nv_bfloat162(__float2bfloat16_rn(v[i].x * inv),
                                       __float2bfloat16_rn(v[i].y * inv));
        fr[i * 2 + 1] = __nv_bfloat162(__float2bfloat16_rn(v[i].z * inv),
                                       __float2bfloat16_rn(v[i].w * inv));
    }
}

// ---------------------------------------------------------------------------
// Kernel B: bf16 mma.sync GEMM, lower-tri tiles, cp.async 3-stage pipeline.
// 4 warps of 64x64 (2x2 warp grid). Schedule = R6/R11 (fastest measured):
// issue(c+2) -> wait(1) -> sync -> compute -> sync.
// ---------------------------------------------------------------------------
extern __shared__ char dynsm[];

__global__ __launch_bounds__(NTHREADS, 2) void gemm_lse_mma() {
    __shared__ float red_r[TM][2];
    __shared__ float red_c[TN][2];

    const int tid  = threadIdx.x;
    const int wid  = tid >> 5;
    const int lane = tid & 31;
    const int wr   = wid & 1;        // warp row (M chunks of 64)
    const int wc   = wid >> 1;       // warp col (N chunks of 64)
    const int g    = lane >> 2;
    const int t    = lane & 3;

    // decode lower-tri pair (bi >= bj)
    int idx = blockIdx.x;
    int bi = (int)((sqrtf(8.0f * (float)idx + 1.0f) - 1.0f) * 0.5f);
    while ((bi + 1) * (bi + 2) / 2 <= idx) bi++;
    while (bi * (bi + 1) / 2 > idx) bi--;
    int bj = idx - bi * (bi + 1) / 2;
    const int r0 = bi * TM;
    const int j0 = bj * TN;
    const bool offdiag = (bi != bj);

    const __nv_bfloat16* srcA = g_f + (size_t)r0 * DIM;
    const __nv_bfloat16* srcB = g_f + (size_t)j0 * DIM;

    const uint32_t smem_base = smem_u32(dynsm);

    const int srow = tid >> 3;       // 0..15; +16 per iter (8 iters = 128 rows)
    const int sseg = tid & 7;

    const int a_row  = wr * 64 + (lane & 15);
    const int a_koff = (lane >> 4) * 16;
    const int b_row  = wc * 64 + (lane & 7) + ((lane >> 4) << 3);
    const int b_koff = ((lane >> 3) & 1) * 16;

    float acc[4][8][4];
#pragma unroll
    for (int mt = 0; mt < 4; mt++)
#pragma unroll
        for (int nt = 0; nt < 8; nt++)
#pragma unroll
            for (int rr = 0; rr < 4; rr++) acc[mt][nt][rr] = 0.f;

    auto issue_chunk = [&](int c, int s) {
        const uint32_t sa = smem_base + s * STAGE_BYTES;
        const int ko = c * KC;
#pragma unroll
        for (int it = 0; it < 8; it++) {
            int row = srow + it * 16;
            uint32_t off = SWZ(row * 128 + sseg * 16);
            cp16(sa + off, srcA + (size_t)row * DIM + ko + sseg * 8);
            cp16(sa + TILE_BYTES + off, srcB + (size_t)row * DIM + ko + sseg * 8);
        }
        asm volatile("cp.async.commit_group;" ::: "memory");
    };

    // prologue: stages 0..STAGES-2
#pragma unroll
    for (int s = 0; s < STAGES - 1; s++) issue_chunk(s, s);

    for (int c = 0; c < NCHUNK; c++) {
        if (c + STAGES - 1 < NCHUNK) {
            issue_chunk(c + STAGES - 1, (c + STAGES - 1) % STAGES);
            asm volatile("cp.async.wait_group %0;" :: "n"(STAGES - 2) : "memory");
        } else {
            asm volatile("cp.async.wait_group 0;" ::: "memory");
        }
        __syncthreads();

        const uint32_t sa = smem_base + (c % STAGES) * STAGE_BYTES;
        const uint32_t sb = sa + TILE_BYTES;

#pragma unroll
        for (int kstep = 0; kstep < 4; kstep++) {
            uint32_t afr[4][4];
#pragma unroll
            for (int mt = 0; mt < 4; mt++) {
                int off = SWZ((a_row + mt * 16) * 128 + kstep * 32 + a_koff);
                ldsm_x4(afr[mt], sa + off);
            }
            uint32_t bfr[8][2];
#pragma unroll
            for (int p = 0; p < 4; p++) {
                uint32_t r[4];
                int off = SWZ((b_row + p * 16) * 128 + kstep * 32 + b_koff);
                ldsm_x4(r, sb + off);
                bfr[2 * p][0] = r[0]; bfr[2 * p][1] = r[1];
                bfr[2 * p + 1][0] = r[2]; bfr[2 * p + 1][1] = r[3];
            }
#pragma unroll
            for (int mt = 0; mt < 4; mt++)
#pragma unroll
                for (int nt = 0; nt < 8; nt++)
                    mma_bf16(acc[mt][nt], afr[mt], bfr[nt][0], bfr[nt][1]);
        }
        __syncthreads();   // all reads of this stage done before reuse
    }

    // ---- epilogue: exp in place; row sums + col sums (off-diag) ----
#pragma unroll
    for (int mt = 0; mt < 4; mt++)
#pragma unroll
        for (int nt = 0; nt < 8; nt++)
#pragma unroll
            for (int rr = 0; rr < 4; rr++)
                acc[mt][nt][rr] = __expf((acc[mt][nt][rr] - 1.0f) * INV_T);

    // row sums: row = wr*64 + mt*16 + hi*8 + g, reduce over t (lanes ^1,^2)
#pragma unroll
    for (int mt = 0; mt < 4; mt++)
#pragma unroll
        for (int hi = 0; hi < 2; hi++) {
            float s = 0.f;
#pragma unroll
            for (int nt = 0; nt < 8; nt++)
                s += acc[mt][nt][hi * 2 + 0] + acc[mt][nt][hi * 2 + 1];
            s += __shfl_xor_sync(0xffffffffu, s, 1);
            s += __shfl_xor_sync(0xffffffffu, s, 2);
            if (t == 0) red_r[wr * 64 + mt * 16 + hi * 8 + g][wc] = s;
        }

    // col sums: col = wc*64 + nt*8 + t*2 + {0,1}; sum over mt, reduce over g
    if (offdiag) {
#pragma unroll
        for (int nt = 0; nt < 8; nt++) {
            float cs0 = 0.f, cs1 = 0.f;
#pragma unroll
            for (int mt = 0; mt < 4; mt++) {
                cs0 += acc[mt][nt][0] + acc[mt][nt][2];
                cs1 += acc[mt][nt][1] + acc[mt][nt][3];
            }
#pragma unroll
            for (int o = 4; o <= 16; o <<= 1) {
                cs0 += __shfl_xor_sync(0xffffffffu, cs0, o);
                cs1 += __shfl_xor_sync(0xffffffffu, cs1, o);
            }
            if (g == 0) {
                red_c[wc * 64 + nt * 8 + t * 2 + 0][wr] = cs0;
                red_c[wc * 64 + nt * 8 + t * 2 + 1][wr] = cs1;
            }
        }
    }
    __syncthreads();

    // 128 threads, one row each
    g_partial[bj][r0 + tid] = red_r[tid][0] + red_r[tid][1];
    if (offdiag)
        g_partial[bi][j0 + tid] = red_c[tid][0] + red_c[tid][1];
}

// ---------------------------------------------------------------------------
// Kernel C: labels (col 0/1), picked dot (uint4-vectorized bf16), lse
// ---------------------------------------------------------------------------
__global__ void pick_kernel(const int* __restrict__ ids,
                            const int* __restrict__ anchor) {
    int row  = blockIdx.x * 8 + threadIdx.y;
    int lane = threadIdx.x;

    int aid       = ids[anchor[0]];
    int same_last = (ids[BROWS - 1] == aid);
    int label;
    if (row == BROWS - 1)
        label = (same_last && (ids[BROWS - 2] == aid)) ? 1 : 0;
    else
        label = ((ids[row] == aid) && same_last) ? 1 : 0;

    const uint4* fi = (const uint4*)(g_f + (size_t)row * DIM);
    const uint4* fc = (const uint4*)(g_f + (size_t)label * DIM);
    // 512 bf16 = 64 uint4; 2 per lane
    float d = dot8_bf16(fi[lane], fc[lane]) +
              dot8_bf16(fi[lane + 32], fc[lane + 32]);

    // parallel partial-slot sum: lanes each grab 2 of the 64 slots
    float rs = g_partial[lane][row] + g_partial[lane + 32][row];

#pragma unroll
    for (int o = 16; o; o >>= 1) {
        d  += __shfl_xor_sync(0xffffffffu, d, o);
        rs += __shfl_xor_sync(0xffffffffu, rs, o);
    }

    if (lane == 0) {
        float lse = INV_T + logf(rs);
        g_rowval[row] = lse - d * INV_T;
    }
}

// ---------------------------------------------------------------------------
// Kernel D: deterministic final reduction (1024 threads)
// ---------------------------------------------------------------------------
__global__ void finalize_kernel(float* __restrict__ out) {
    __shared__ float sm[32];
    int tdx = threadIdx.x;
    float s = 0.f;
#pragma unroll
    for (int i = 0; i < 8; i++) s += g_rowval[tdx + i * 1024];
#pragma unroll
    for (int o = 16; o; o >>= 1) s += __shfl_xor_sync(0xffffffffu, s, o);
    if ((tdx & 31) == 0) sm[tdx >> 5] = s;
    __syncthreads();
    if (tdx < 32) {
        float v = sm[tdx];
#pragma unroll
        for (int o = 16; o; o >>= 1) v += __shfl_xor_sync(0xffffffffu, v, o);
        if (tdx == 0) out[0] = v / (float)BROWS;
    }
}

// ---------------------------------------------------------------------------
extern "C" void kernel_launch(void* const* d_in, const int* in_sizes, int n_in,
                              void* d_out, int out_size) {
    const float* feat   = (const float*)d_in[0];
    const int*   ids    = (const int*)d_in[1];
    const int*   anchor = (const int*)d_in[2];
    float*       out    = (float*)d_out;

    cudaFuncSetAttribute(gemm_lse_mma,
                         cudaFuncAttributeMaxDynamicSharedMemorySize, SMEM_BYTES);

    dim3 b32x8(32, 8);
    normalize_kernel<<<BROWS / 8, b32x8>>>(feat);

    gemm_lse_mma<<<NTILES, NTHREADS, SMEM_BYTES>>>();

    pick_kernel<<<BROWS / 8, b32x8>>>(ids, anchor);
    finalize_kernel<<<1, 1024>>>(out);
}

// round 14
// speedup vs baseline: 1.1593x; 1.0072x over previous
#include <cuda_runtime.h>
#include <cuda_bf16.h>
#include <cstdint>
#include <math.h>

// Problem constants
#define BROWS 8192
#define DIM   512
#define INV_T 14.285714285714286f   // 1/0.07

// Tiling: CTA 128x128 = 4 warps x (64x64), mma m16n8k16 bf16
#define TM 128
#define TN 128
#define KC 64                        // bf16 elements per chunk (128B rows)
#define NCHUNK (DIM / KC)            // 8
#define NB (BROWS / TM)              // 64 blocks per dim
#define NTILES (NB * (NB + 1) / 2)   // 2080 lower-tri tiles
#define NTHREADS 128
#define PICK_BLOCKS (BROWS / 8)      // 1024

#define TILE_BYTES  (128 * 128)      // one 128-row x 128B tile (16 KB)
#define STAGE_BYTES (2 * TILE_BYTES) // A + B (32 KB)
#define STAGES 3
#define SMEM_BYTES  (STAGES * STAGE_BYTES)   // 96 KB -> occ 2

#define SWZ(o) ((o) ^ (((o) >> 3) & 0x70))

// Scratch (static device globals — no allocation)
__device__ __nv_bfloat16 g_f[BROWS * DIM];   // bf16 normalized features (8 MB)
__device__ float g_partial[NB][BROWS];       // per-block exp row sums
__device__ float g_rowval[BROWS];
__device__ unsigned g_done;                  // pick completion counter

// ---------------------------------------------------------------------------
__device__ __forceinline__ uint32_t smem_u32(const void* p) {
    uint32_t a;
    asm("{ .reg .u64 t; cvta.to.shared.u64 t, %1; cvt.u32.u64 %0, t; }"
        : "=r"(a) : "l"(p));
    return a;
}
__device__ __forceinline__ void cp16(uint32_t dst, const void* src) {
    asm volatile("cp.async.cg.shared.global [%0], [%1], 16;"
                 :: "r"(dst), "l"(src) : "memory");
}
__device__ __forceinline__ void ldsm_x4(uint32_t* r, uint32_t addr) {
    asm volatile("ldmatrix.sync.aligned.m8n8.x4.shared.b16 {%0,%1,%2,%3}, [%4];"
                 : "=r"(r[0]), "=r"(r[1]), "=r"(r[2]), "=r"(r[3]) : "r"(addr));
}
__device__ __forceinline__ void mma_bf16(float* c, const uint32_t* a,
                                         uint32_t b0, uint32_t b1) {
    asm volatile(
        "mma.sync.aligned.m16n8k16.row.col.f32.bf16.bf16.f32 "
        "{%0,%1,%2,%3}, {%4,%5,%6,%7}, {%8,%9}, {%0,%1,%2,%3};"
        : "+f"(c[0]), "+f"(c[1]), "+f"(c[2]), "+f"(c[3])
        : "r"(a[0]), "r"(a[1]), "r"(a[2]), "r"(a[3]), "r"(b0), "r"(b1));
}
__device__ __forceinline__ float dot8_bf16(uint4 a, uint4 b) {
    const __nv_bfloat162* pa = (const __nv_bfloat162*)&a;
    const __nv_bfloat162* pb = (const __nv_bfloat162*)&b;
    float s = 0.f;
#pragma unroll
    for (int i = 0; i < 4; i++) {
        float2 fa = __bfloat1622float2(pa[i]);
        float2 fb = __bfloat1622float2(pb[i]);
        s = fmaf(fa.x, fb.x, s);
        s = fmaf(fa.y, fb.y, s);
    }
    return s;
}

// ---------------------------------------------------------------------------
// Kernel A: row L2-normalize + round to bf16 (float4 I/O); resets counter.
// ---------------------------------------------------------------------------
__global__ void normalize_kernel(const float* __restrict__ x) {
    if (blockIdx.x == 0 && threadIdx.x == 0 && threadIdx.y == 0) g_done = 0;
    int row  = blockIdx.x * 8 + threadIdx.y;
    int lane = threadIdx.x;
    const float4* xr = (const float4*)(x + (size_t)row * DIM) + lane * 4;
    float4 v[4];
    float s = 0.f;
#pragma unroll
    for (int i = 0; i < 4; i++) {
        v[i] = xr[i];
        s += v[i].x * v[i].x + v[i].y * v[i].y + v[i].z * v[i].z + v[i].w * v[i].w;
    }
#pragma unroll
    for (int o = 16; o; o >>= 1) s += __shfl_xor_sync(0xffffffffu, s, o);
    float inv = 1.0f / fmaxf(sqrtf(s), 1e-12f);
    __nv_bfloat162* fr = (__nv_bfloat162*)(g_f + (size_t)row * DIM) + lane * 8;
#pragma unroll
    for (int i = 0; i < 4; i++) {
        fr[i * 2 + 0] = __nv_bfloat162(__float2bfloat16_rn(v[i].x * inv),
                                       __float2bfloat16_rn(v[i].y * inv));
        fr[i * 2 + 1] = __nv_bfloat162(__float2bfloat16_rn(v[i].z * inv),
                                       __float2bfloat16_rn(v[i].w * inv));
    }
}

// ---------------------------------------------------------------------------
// Kernel B: bf16 mma.sync GEMM, lower-tri tiles, cp.async 3-stage pipeline.
// 4 warps of 64x64 (2x2 warp grid). Schedule = R6/R11 (fastest measured):
// issue(c+2) -> wait(1) -> sync -> compute -> sync.  (VERBATIM from R11.)
// ---------------------------------------------------------------------------
extern __shared__ char dynsm[];

__global__ __launch_bounds__(NTHREADS, 2) void gemm_lse_mma() {
    __shared__ float red_r[TM][2];
    __shared__ float red_c[TN][2];

    const int tid  = threadIdx.x;
    const int wid  = tid >> 5;
    const int lane = tid & 31;
    const int wr   = wid & 1;        // warp row (M chunks of 64)
    const int wc   = wid >> 1;       // warp col (N chunks of 64)
    const int g    = lane >> 2;
    const int t    = lane & 3;

    // decode lower-tri pair (bi >= bj)
    int idx = blockIdx.x;
    int bi = (int)((sqrtf(8.0f * (float)idx + 1.0f) - 1.0f) * 0.5f);
    while ((bi + 1) * (bi + 2) / 2 <= idx) bi++;
    while (bi * (bi + 1) / 2 > idx) bi--;
    int bj = idx - bi * (bi + 1) / 2;
    const int r0 = bi * TM;
    const int j0 = bj * TN;
    const bool offdiag = (bi != bj);

    const __nv_bfloat16* srcA = g_f + (size_t)r0 * DIM;
    const __nv_bfloat16* srcB = g_f + (size_t)j0 * DIM;

    const uint32_t smem_base = smem_u32(dynsm);

    const int srow = tid >> 3;       // 0..15; +16 per iter (8 iters = 128 rows)
    const int sseg = tid & 7;

    const int a_row  = wr * 64 + (lane & 15);
    const int a_koff = (lane >> 4) * 16;
    const int b_row  = wc * 64 + (lane & 7) + ((lane >> 4) << 3);
    const int b_koff = ((lane >> 3) & 1) * 16;

    float acc[4][8][4];
#pragma unroll
    for (int mt = 0; mt < 4; mt++)
#pragma unroll
        for (int nt = 0; nt < 8; nt++)
#pragma unroll
            for (int rr = 0; rr < 4; rr++) acc[mt][nt][rr] = 0.f;

    auto issue_chunk = [&](int c, int s) {
        const uint32_t sa = smem_base + s * STAGE_BYTES;
        const int ko = c * KC;
#pragma unroll
        for (int it = 0; it < 8; it++) {
            int row = srow + it * 16;
            uint32_t off = SWZ(row * 128 + sseg * 16);
            cp16(sa + off, srcA + (size_t)row * DIM + ko + sseg * 8);
            cp16(sa + TILE_BYTES + off, srcB + (size_t)row * DIM + ko + sseg * 8);
        }
        asm volatile("cp.async.commit_group;" ::: "memory");
    };

    // prologue: stages 0..STAGES-2
#pragma unroll
    for (int s = 0; s < STAGES - 1; s++) issue_chunk(s, s);

    for (int c = 0; c < NCHUNK; c++) {
        if (c + STAGES - 1 < NCHUNK) {
            issue_chunk(c + STAGES - 1, (c + STAGES - 1) % STAGES);
            asm volatile("cp.async.wait_group %0;" :: "n"(STAGES - 2) : "memory");
        } else {
            asm volatile("cp.async.wait_group 0;" ::: "memory");
        }
        __syncthreads();

        const uint32_t sa = smem_base + (c % STAGES) * STAGE_BYTES;
        const uint32_t sb = sa + TILE_BYTES;

#pragma unroll
        for (int kstep = 0; kstep < 4; kstep++) {
            uint32_t afr[4][4];
#pragma unroll
            for (int mt = 0; mt < 4; mt++) {
                int off = SWZ((a_row + mt * 16) * 128 + kstep * 32 + a_koff);
                ldsm_x4(afr[mt], sa + off);
            }
            uint32_t bfr[8][2];
#pragma unroll
            for (int p = 0; p < 4; p++) {
                uint32_t r[4];
                int off = SWZ((b_row + p * 16) * 128 + kstep * 32 + b_koff);
                ldsm_x4(r, sb + off);
                bfr[2 * p][0] = r[0]; bfr[2 * p][1] = r[1];
                bfr[2 * p + 1][0] = r[2]; bfr[2 * p + 1][1] = r[3];
            }
#pragma unroll
            for (int mt = 0; mt < 4; mt++)
#pragma unroll
                for (int nt = 0; nt < 8; nt++)
                    mma_bf16(acc[mt][nt], afr[mt], bfr[nt][0], bfr[nt][1]);
        }
        __syncthreads();   // all reads of this stage done before reuse
    }

    // ---- epilogue: exp in place; row sums + col sums (off-diag) ----
#pragma unroll
    for (int mt = 0; mt < 4; mt++)
#pragma unroll
        for (int nt = 0; nt < 8; nt++)
#pragma unroll
            for (int rr = 0; rr < 4; rr++)
                acc[mt][nt][rr] = __expf((acc[mt][nt][rr] - 1.0f) * INV_T);

    // row sums: row = wr*64 + mt*16 + hi*8 + g, reduce over t (lanes ^1,^2)
#pragma unroll
    for (int mt = 0; mt < 4; mt++)
#pragma unroll
        for (int hi = 0; hi < 2; hi++) {
            float s = 0.f;
#pragma unroll
            for (int nt = 0; nt < 8; nt++)
                s += acc[mt][nt][hi * 2 + 0] + acc[mt][nt][hi * 2 + 1];
            s += __shfl_xor_sync(0xffffffffu, s, 1);
            s += __shfl_xor_sync(0xffffffffu, s, 2);
            if (t == 0) red_r[wr * 64 + mt * 16 + hi * 8 + g][wc] = s;
        }

    // col sums: col = wc*64 + nt*8 + t*2 + {0,1}; sum over mt, reduce over g
    if (offdiag) {
#pragma unroll
        for (int nt = 0; nt < 8; nt++) {
            float cs0 = 0.f, cs1 = 0.f;
#pragma unroll
            for (int mt = 0; mt < 4; mt++) {
                cs0 += acc[mt][nt][0] + acc[mt][nt][2];
                cs1 += acc[mt][nt][1] + acc[mt][nt][3];
            }
#pragma unroll
            for (int o = 4; o <= 16; o <<= 1) {
                cs0 += __shfl_xor_sync(0xffffffffu, cs0, o);
                cs1 += __shfl_xor_sync(0xffffffffu, cs1, o);
            }
            if (g == 0) {
                red_c[wc * 64 + nt * 8 + t * 2 + 0][wr] = cs0;
                red_c[wc * 64 + nt * 8 + t * 2 + 1][wr] = cs1;
            }
        }
    }
    __syncthreads();

    // 128 threads, one row each
    g_partial[bj][r0 + tid] = red_r[tid][0] + red_r[tid][1];
    if (offdiag)
        g_partial[bi][j0 + tid] = red_c[tid][0] + red_c[tid][1];
}

// ---------------------------------------------------------------------------
// Kernel C: fused pick + final reduction. Each block writes 8 rowvals; the
// LAST block to finish reduces all 8192 in fixed order -> deterministic.
// ---------------------------------------------------------------------------
__global__ void pick_finalize_kernel(const int* __restrict__ ids,
                                     const int* __restrict__ anchor,
                                     float* __restrict__ out) {
    __shared__ bool is_last;
    __shared__ float sm[8];
    int row  = blockIdx.x * 8 + threadIdx.y;
    int lane = threadIdx.x;
    int tid  = threadIdx.y * 32 + threadIdx.x;

    int aid       = ids[anchor[0]];
    int same_last = (ids[BROWS - 1] == aid);
    int label;
    if (row == BROWS - 1)
        label = (same_last && (ids[BROWS - 2] == aid)) ? 1 : 0;
    else
        label = ((ids[row] == aid) && same_last) ? 1 : 0;

    const uint4* fi = (const uint4*)(g_f + (size_t)row * DIM);
    const uint4* fc = (const uint4*)(g_f + (size_t)label * DIM);
    float d = dot8_bf16(fi[lane], fc[lane]) +
              dot8_bf16(fi[lane + 32], fc[lane + 32]);

    float rs = g_partial[lane][row] + g_partial[lane + 32][row];

#pragma unroll
    for (int o = 16; o; o >>= 1) {
        d  += __shfl_xor_sync(0xffffffffu, d, o);
        rs += __shfl_xor_sync(0xffffffffu, rs, o);
    }

    if (lane == 0) {
        float lse = INV_T + logf(rs);
        g_rowval[row] = lse - d * INV_T;
    }

    // ---- completion detection + final reduction in the last block ----
    __threadfence();
    __syncthreads();
    if (tid == 0)
        is_last = (atomicAdd(&g_done, 1u) == PICK_BLOCKS - 1);
    __syncthreads();

    if (is_last) {
        float s = 0.f;
#pragma unroll
        for (int i = 0; i < 32; i++) s += g_rowval[tid + i * 256];
#pragma unroll
        for (int o = 16; o; o >>= 1) s += __shfl_xor_sync(0xffffffffu, s, o);
        if ((tid & 31) == 0) sm[tid >> 5] = s;
        __syncthreads();
        if (tid < 8) {
            float v = sm[tid];
#pragma unroll
            for (int o = 4; o; o >>= 1) v += __shfl_xor_sync(0xffu, v, o);
            if (tid == 0) out[0] = v / (float)BROWS;
        }
    }
}

// ---------------------------------------------------------------------------
extern "C" void kernel_launch(void* const* d_in, const int* in_sizes, int n_in,
                              void* d_out, int out_size) {
    const float* feat   = (const float*)d_in[0];
    const int*   ids    = (const int*)d_in[1];
    const int*   anchor = (const int*)d_in[2];
    float*       out    = (float*)d_out;

    cudaFuncSetAttribute(gemm_lse_mma,
                         cudaFuncAttributeMaxDynamicSharedMemorySize, SMEM_BYTES);

    dim3 b32x8(32, 8);
    normalize_kernel<<<BROWS / 8, b32x8>>>(feat);

    gemm_lse_mma<<<NTILES, NTHREADS, SMEM_BYTES>>>();

    pick_finalize_kernel<<<PICK_BLOCKS, b32x8>>>(ids, anchor, out);
}

// round 15
// speedup vs baseline: 1.2081x; 1.0421x over previous
#include <cuda_runtime.h>
#include <cuda_bf16.h>
#include <cstdint>
#include <math.h>

// Problem constants
#define BROWS 8192
#define DIM   512
#define INV_T 14.285714285714286f   // 1/0.07

// Tiling: CTA 128x128 = 4 warps x (64x64), mma m16n8k16 bf16
#define TM 128
#define TN 128
#define KC 64                        // bf16 elements per chunk (128B rows)
#define NCHUNK (DIM / KC)            // 8
#define NB (BROWS / TM)              // 64 blocks per dim
#define NTILES (NB * (NB + 1) / 2)   // 2080 lower-tri tiles
#define NTHREADS 128
#define PICK_BLOCKS (BROWS / 8)      // 1024

#define TILE_BYTES  (128 * 128)      // one 128-row x 128B tile (16 KB)
#define STAGE_BYTES (2 * TILE_BYTES) // A + B (32 KB)
#define STAGES 3
#define SMEM_BYTES  (STAGES * STAGE_BYTES)   // 96 KB -> occ 2

#define SWZ(o) ((o) ^ (((o) >> 3) & 0x70))

// Scratch (static device globals — no allocation)
__device__ __nv_bfloat16 g_f[BROWS * DIM];   // bf16 normalized features (8 MB)
__device__ float g_partial[NB][BROWS];       // per-block exp row sums
__device__ float g_rowval[BROWS];
__device__ unsigned g_done;                  // pick completion counter

// ---------------------------------------------------------------------------
__device__ __forceinline__ uint32_t smem_u32(const void* p) {
    uint32_t a;
    asm("{ .reg .u64 t; cvta.to.shared.u64 t, %1; cvt.u32.u64 %0, t; }"
        : "=r"(a) : "l"(p));
    return a;
}
__device__ __forceinline__ void cp16(uint32_t dst, const void* src) {
    asm volatile("cp.async.cg.shared.global [%0], [%1], 16;"
                 :: "r"(dst), "l"(src) : "memory");
}
__device__ __forceinline__ void ldsm_x4(uint32_t* r, uint32_t addr) {
    asm volatile("ldmatrix.sync.aligned.m8n8.x4.shared.b16 {%0,%1,%2,%3}, [%4];"
                 : "=r"(r[0]), "=r"(r[1]), "=r"(r[2]), "=r"(r[3]) : "r"(addr));
}
__device__ __forceinline__ void mma_bf16(float* c, const uint32_t* a,
                                         uint32_t b0, uint32_t b1) {
    asm volatile(
        "mma.sync.aligned.m16n8k16.row.col.f32.bf16.bf16.f32 "
        "{%0,%1,%2,%3}, {%4,%5,%6,%7}, {%8,%9}, {%0,%1,%2,%3};"
        : "+f"(c[0]), "+f"(c[1]), "+f"(c[2]), "+f"(c[3])
        : "r"(a[0]), "r"(a[1]), "r"(a[2]), "r"(a[3]), "r"(b0), "r"(b1));
}
__device__ __forceinline__ float dot8_bf16(uint4 a, uint4 b) {
    const __nv_bfloat162* pa = (const __nv_bfloat162*)&a;
    const __nv_bfloat162* pb = (const __nv_bfloat162*)&b;
    float s = 0.f;
#pragma unroll
    for (int i = 0; i < 4; i++) {
        float2 fa = __bfloat1622float2(pa[i]);
        float2 fb = __bfloat1622float2(pb[i]);
        s = fmaf(fa.x, fb.x, s);
        s = fmaf(fa.y, fb.y, s);
    }
    return s;
}

// ---------------------------------------------------------------------------
// Kernel A: row L2-normalize + round to bf16. 4 rows per warp, 16 loads in
// flight per thread (latency-bound fix: MLP 4 -> 16). Resets g_done.
// ---------------------------------------------------------------------------
__global__ void normalize_kernel(const float* __restrict__ x) {
    if (blockIdx.x == 0 && threadIdx.x == 0) g_done = 0;
    const int warp = threadIdx.x >> 5;
    const int lane = threadIdx.x & 31;
    const int rbase = blockIdx.x * 32 + warp * 4;

    float4 v[4][4];
    // 16 independent loads issued back-to-back
#pragma unroll
    for (int r = 0; r < 4; r++) {
        const float4* xr = (const float4*)(x + (size_t)(rbase + r) * DIM);
#pragma unroll
        for (int i = 0; i < 4; i++)
            v[r][i] = xr[lane + i * 32];
    }

    float s[4];
#pragma unroll
    for (int r = 0; r < 4; r++) {
        float a = 0.f;
#pragma unroll
        for (int i = 0; i < 4; i++)
            a += v[r][i].x * v[r][i].x + v[r][i].y * v[r][i].y +
                 v[r][i].z * v[r][i].z + v[r][i].w * v[r][i].w;
        s[r] = a;
    }
#pragma unroll
    for (int o = 16; o; o >>= 1)
#pragma unroll
        for (int r = 0; r < 4; r++)
            s[r] += __shfl_xor_sync(0xffffffffu, s[r], o);

#pragma unroll
    for (int r = 0; r < 4; r++) {
        float inv = 1.0f / fmaxf(sqrtf(s[r]), 1e-12f);
        uint2* dst = (uint2*)(g_f + (size_t)(rbase + r) * DIM);
#pragma unroll
        for (int i = 0; i < 4; i++) {
            __nv_bfloat162 lo(__float2bfloat16_rn(v[r][i].x * inv),
                              __float2bfloat16_rn(v[r][i].y * inv));
            __nv_bfloat162 hi(__float2bfloat16_rn(v[r][i].z * inv),
                              __float2bfloat16_rn(v[r][i].w * inv));
            uint2 pk;
            pk.x = *(uint32_t*)&lo;
            pk.y = *(uint32_t*)&hi;
            dst[lane + i * 32] = pk;
        }
    }
}

// ---------------------------------------------------------------------------
// Kernel B: bf16 mma.sync GEMM, lower-tri tiles, cp.async 3-stage pipeline.
// 4 warps of 64x64 (2x2 warp grid). Schedule = R6/R11 (fastest measured):
// issue(c+2) -> wait(1) -> sync -> compute -> sync.  (VERBATIM from R11.)
// ---------------------------------------------------------------------------
extern __shared__ char dynsm[];

__global__ __launch_bounds__(NTHREADS, 2) void gemm_lse_mma() {
    __shared__ float red_r[TM][2];
    __shared__ float red_c[TN][2];

    const int tid  = threadIdx.x;
    const int wid  = tid >> 5;
    const int lane = tid & 31;
    const int wr   = wid & 1;        // warp row (M chunks of 64)
    const int wc   = wid >> 1;       // warp col (N chunks of 64)
    const int g    = lane >> 2;
    const int t    = lane & 3;

    // decode lower-tri pair (bi >= bj)
    int idx = blockIdx.x;
    int bi = (int)((sqrtf(8.0f * (float)idx + 1.0f) - 1.0f) * 0.5f);
    while ((bi + 1) * (bi + 2) / 2 <= idx) bi++;
    while (bi * (bi + 1) / 2 > idx) bi--;
    int bj = idx - bi * (bi + 1) / 2;
    const int r0 = bi * TM;
    const int j0 = bj * TN;
    const bool offdiag = (bi != bj);

    const __nv_bfloat16* srcA = g_f + (size_t)r0 * DIM;
    const __nv_bfloat16* srcB = g_f + (size_t)j0 * DIM;

    const uint32_t smem_base = smem_u32(dynsm);

    const int srow = tid >> 3;       // 0..15; +16 per iter (8 iters = 128 rows)
    const int sseg = tid & 7;

    const int a_row  = wr * 64 + (lane & 15);
    const int a_koff = (lane >> 4) * 16;
    const int b_row  = wc * 64 + (lane & 7) + ((lane >> 4) << 3);
    const int b_koff = ((lane >> 3) & 1) * 16;

    float acc[4][8][4];
#pragma unroll
    for (int mt = 0; mt < 4; mt++)
#pragma unroll
        for (int nt = 0; nt < 8; nt++)
#pragma unroll
            for (int rr = 0; rr < 4; rr++) acc[mt][nt][rr] = 0.f;

    auto issue_chunk = [&](int c, int s) {
        const uint32_t sa = smem_base + s * STAGE_BYTES;
        const int ko = c * KC;
#pragma unroll
        for (int it = 0; it < 8; it++) {
            int row = srow + it * 16;
            uint32_t off = SWZ(row * 128 + sseg * 16);
            cp16(sa + off, srcA + (size_t)row * DIM + ko + sseg * 8);
            cp16(sa + TILE_BYTES + off, srcB + (size_t)row * DIM + ko + sseg * 8);
        }
        asm volatile("cp.async.commit_group;" ::: "memory");
    };

    // prologue: stages 0..STAGES-2
#pragma unroll
    for (int s = 0; s < STAGES - 1; s++) issue_chunk(s, s);

    for (int c = 0; c < NCHUNK; c++) {
        if (c + STAGES - 1 < NCHUNK) {
            issue_chunk(c + STAGES - 1, (c + STAGES - 1) % STAGES);
            asm volatile("cp.async.wait_group %0;" :: "n"(STAGES - 2) : "memory");
        } else {
            asm volatile("cp.async.wait_group 0;" ::: "memory");
        }
        __syncthreads();

        const uint32_t sa = smem_base + (c % STAGES) * STAGE_BYTES;
        const uint32_t sb = sa + TILE_BYTES;

#pragma unroll
        for (int kstep = 0; kstep < 4; kstep++) {
            uint32_t afr[4][4];
#pragma unroll
            for (int mt = 0; mt < 4; mt++) {
                int off = SWZ((a_row + mt * 16) * 128 + kstep * 32 + a_koff);
                ldsm_x4(afr[mt], sa + off);
            }
            uint32_t bfr[8][2];
#pragma unroll
            for (int p = 0; p < 4; p++) {
                uint32_t r[4];
                int off = SWZ((b_row + p * 16) * 128 + kstep * 32 + b_koff);
                ldsm_x4(r, sb + off);
                bfr[2 * p][0] = r[0]; bfr[2 * p][1] = r[1];
                bfr[2 * p + 1][0] = r[2]; bfr[2 * p + 1][1] = r[3];
            }
#pragma unroll
            for (int mt = 0; mt < 4; mt++)
#pragma unroll
                for (int nt = 0; nt < 8; nt++)
                    mma_bf16(acc[mt][nt], afr[mt], bfr[nt][0], bfr[nt][1]);
        }
        __syncthreads();   // all reads of this stage done before reuse
    }

    // ---- epilogue: exp in place; row sums + col sums (off-diag) ----
#pragma unroll
    for (int mt = 0; mt < 4; mt++)
#pragma unroll
        for (int nt = 0; nt < 8; nt++)
#pragma unroll
            for (int rr = 0; rr < 4; rr++)
                acc[mt][nt][rr] = __expf((acc[mt][nt][rr] - 1.0f) * INV_T);

    // row sums: row = wr*64 + mt*16 + hi*8 + g, reduce over t (lanes ^1,^2)
#pragma unroll
    for (int mt = 0; mt < 4; mt++)
#pragma unroll
        for (int hi = 0; hi < 2; hi++) {
            float s = 0.f;
#pragma unroll
            for (int nt = 0; nt < 8; nt++)
                s += acc[mt][nt][hi * 2 + 0] + acc[mt][nt][hi * 2 + 1];
            s += __shfl_xor_sync(0xffffffffu, s, 1);
            s += __shfl_xor_sync(0xffffffffu, s, 2);
            if (t == 0) red_r[wr * 64 + mt * 16 + hi * 8 + g][wc] = s;
        }

    // col sums: col = wc*64 + nt*8 + t*2 + {0,1}; sum over mt, reduce over g
    if (offdiag) {
#pragma unroll
        for (int nt = 0; nt < 8; nt++) {
            float cs0 = 0.f, cs1 = 0.f;
#pragma unroll
            for (int mt = 0; mt < 4; mt++) {
                cs0 += acc[mt][nt][0] + acc[mt][nt][2];
                cs1 += acc[mt][nt][1] + acc[mt][nt][3];
            }
#pragma unroll
            for (int o = 4; o <= 16; o <<= 1) {
                cs0 += __shfl_xor_sync(0xffffffffu, cs0, o);
                cs1 += __shfl_xor_sync(0xffffffffu, cs1, o);
            }
            if (g == 0) {
                red_c[wc * 64 + nt * 8 + t * 2 + 0][wr] = cs0;
                red_c[wc * 64 + nt * 8 + t * 2 + 1][wr] = cs1;
            }
        }
    }
    __syncthreads();

    // 128 threads, one row each
    g_partial[bj][r0 + tid] = red_r[tid][0] + red_r[tid][1];
    if (offdiag)
        g_partial[bi][j0 + tid] = red_c[tid][0] + red_c[tid][1];
}

// ---------------------------------------------------------------------------
// Kernel C: fused pick + final reduction. Each block writes 8 rowvals; the
// LAST block to finish reduces all 8192 in fixed order -> deterministic.
// ---------------------------------------------------------------------------
__global__ void pick_finalize_kernel(const int* __restrict__ ids,
                                     const int* __restrict__ anchor,
                                     float* __restrict__ out) {
    __shared__ bool is_last;
    __shared__ float sm[8];
    int row  = blockIdx.x * 8 + threadIdx.y;
    int lane = threadIdx.x;
    int tid  = threadIdx.y * 32 + threadIdx.x;

    int aid       = ids[anchor[0]];
    int same_last = (ids[BROWS - 1] == aid);
    int label;
    if (row == BROWS - 1)
        label = (same_last && (ids[BROWS - 2] == aid)) ? 1 : 0;
    else
        label = ((ids[row] == aid) && same_last) ? 1 : 0;

    const uint4* fi = (const uint4*)(g_f + (size_t)row * DIM);
    const uint4* fc = (const uint4*)(g_f + (size_t)label * DIM);
    float d = dot8_bf16(fi[lane], fc[lane]) +
              dot8_bf16(fi[lane + 32], fc[lane + 32]);

    float rs = g_partial[lane][row] + g_partial[lane + 32][row];

#pragma unroll
    for (int o = 16; o; o >>= 1) {
        d  += __shfl_xor_sync(0xffffffffu, d, o);
        rs += __shfl_xor_sync(0xffffffffu, rs, o);
    }

    if (lane == 0) {
        float lse = INV_T + logf(rs);
        g_rowval[row] = lse - d * INV_T;
    }

    // ---- completion detection + final reduction in the last block ----
    __threadfence();
    __syncthreads();
    if (tid == 0)
        is_last = (atomicAdd(&g_done, 1u) == PICK_BLOCKS - 1);
    __syncthreads();

    if (is_last) {
        float s = 0.f;
#pragma unroll
        for (int i = 0; i < 32; i++) s += g_rowval[tid + i * 256];
#pragma unroll
        for (int o = 16; o; o >>= 1) s += __shfl_xor_sync(0xffffffffu, s, o);
        if ((tid & 31) == 0) sm[tid >> 5] = s;
        __syncthreads();
        if (tid < 8) {
            float v = sm[tid];
#pragma unroll
            for (int o = 4; o; o >>= 1) v += __shfl_xor_sync(0xffu, v, o);
            if (tid == 0) out[0] = v / (float)BROWS;
        }
    }
}

// ---------------------------------------------------------------------------
extern "C" void kernel_launch(void* const* d_in, const int* in_sizes, int n_in,
                              void* d_out, int out_size) {
    const float* feat   = (const float*)d_in[0];
    const int*   ids    = (const int*)d_in[1];
    const int*   anchor = (const int*)d_in[2];
    float*       out    = (float*)d_out;

    cudaFuncSetAttribute(gemm_lse_mma,
                         cudaFuncAttributeMaxDynamicSharedMemorySize, SMEM_BYTES);

    normalize_kernel<<<BROWS / 32, 256>>>(feat);

    gemm_lse_mma<<<NTILES, NTHREADS, SMEM_BYTES>>>();

    dim3 b32x8(32, 8);
    pick_finalize_kernel<<<PICK_BLOCKS, b32x8>>>(ids, anchor, out);
}